// round 3
// baseline (speedup 1.0000x reference)
#include <cuda_runtime.h>
#include <cstdint>

#define N_NODES 100000
#define N_EDGES 1600000
#define IN_F    256
#define HID     128
#define OUTF    64

// Scratch (device globals: allocation-free per harness rules)
__device__ float g_h1[(size_t)N_NODES * HID];   // X@W1
__device__ float g_h2[(size_t)N_NODES * HID];   // A @ h1
__device__ float g_h4[(size_t)N_NODES * OUTF];  // relu(h2+b1)@W2
__device__ int   g_cnt[N_NODES];                // per-row edge count
__device__ int   g_off[N_NODES + 1];            // CSR offsets
__device__ int   g_cur[N_NODES];                // scatter cursors
__device__ int   g_perm[N_EDGES];               // edge permutation (CSR order)

__device__ __forceinline__ uint32_t f2tf32(float f) {
    uint32_t u;
    asm("cvt.rna.tf32.f32 %0, %1;" : "=r"(u) : "f"(f));
    return u;
}

__device__ __forceinline__ void mma_tf32(float c[4], const uint32_t a[4], const uint32_t b[2]) {
    asm volatile(
        "mma.sync.aligned.m16n8k8.row.col.f32.tf32.tf32.f32 "
        "{%0,%1,%2,%3}, {%4,%5,%6,%7}, {%8,%9}, {%0,%1,%2,%3};"
        : "+f"(c[0]), "+f"(c[1]), "+f"(c[2]), "+f"(c[3])
        : "r"(a[0]), "r"(a[1]), "r"(a[2]), "r"(a[3]), "r"(b[0]), "r"(b[1]));
}

// ===========================================================================
// CSR build
// ===========================================================================
__global__ void csr_zero_kernel() {
    int i = blockIdx.x * blockDim.x + threadIdx.x;
    if (i < N_NODES) g_cnt[i] = 0;
}

__global__ void csr_count_kernel(const int* __restrict__ row) {
    int e = blockIdx.x * blockDim.x + threadIdx.x;
    if (e < N_EDGES) atomicAdd(&g_cnt[__ldg(row + e)], 1);
}

// Single block, 1024 threads; each thread scans a contiguous chunk.
__global__ __launch_bounds__(1024) void csr_scan_kernel() {
    __shared__ int ssum[1024];
    const int t  = threadIdx.x;
    const int CH = (N_NODES + 1023) / 1024;   // 98
    int lo = t * CH;
    int hi = lo + CH; if (hi > N_NODES) hi = N_NODES;
    if (lo > N_NODES) lo = N_NODES;

    int s = 0;
    for (int i = lo; i < hi; i++) s += g_cnt[i];
    ssum[t] = s;
    __syncthreads();

    // inclusive Hillis-Steele scan
    for (int d = 1; d < 1024; d <<= 1) {
        int add = (t >= d) ? ssum[t - d] : 0;
        __syncthreads();
        ssum[t] += add;
        __syncthreads();
    }

    int run = ssum[t] - s;   // exclusive prefix of this chunk
    for (int i = lo; i < hi; i++) {
        g_off[i] = run;
        g_cur[i] = run;
        run += g_cnt[i];
    }
    if (t == 1023) g_off[N_NODES] = run;   // == N_EDGES
}

__global__ void csr_scatter_kernel(const int* __restrict__ row) {
    int e = blockIdx.x * blockDim.x + threadIdx.x;
    if (e < N_EDGES) {
        int r = __ldg(row + e);
        int p = atomicAdd(&g_cur[r], 1);
        g_perm[p] = e;
    }
}

// ===========================================================================
// GEMM1 (TF32 tensor): g_h1[M,128] = X[M,256] @ W1[256,128]
// Block tile 128x128, BK=32, 256 threads = 8 warps in 4(M)x2(N).
// ===========================================================================
#define G1_STRIDE 132
__global__ __launch_bounds__(256) void gemm1_tf32_kernel(const float* __restrict__ X,
                                                         const float* __restrict__ W1) {
    __shared__ uint32_t As[32 * G1_STRIDE];  // [k][m]
    __shared__ uint32_t Bs[32 * G1_STRIDE];  // [k][n]

    const int tid  = threadIdx.x;
    const int warp = tid >> 5;
    const int lane = tid & 31;
    const int wm   = warp >> 1;
    const int wn   = warp & 1;
    const int brow = blockIdx.x * 128;

    const int grp = lane >> 2;
    const int tig = lane & 3;

    float c[2][8][4];
#pragma unroll
    for (int mt = 0; mt < 2; mt++)
#pragma unroll
        for (int nt = 0; nt < 8; nt++)
#pragma unroll
            for (int i = 0; i < 4; i++) c[mt][nt][i] = 0.f;

    for (int k0 = 0; k0 < IN_F; k0 += 32) {
#pragma unroll
        for (int i = 0; i < 4; i++) {
            int f  = tid + i * 256;
            int r  = f >> 3;
            int kk = (f & 7) << 2;
            int gr = brow + r;
            float4 v = make_float4(0.f, 0.f, 0.f, 0.f);
            if (gr < N_NODES) v = *(const float4*)(X + (size_t)gr * IN_F + k0 + kk);
            As[(kk + 0) * G1_STRIDE + r] = f2tf32(v.x);
            As[(kk + 1) * G1_STRIDE + r] = f2tf32(v.y);
            As[(kk + 2) * G1_STRIDE + r] = f2tf32(v.z);
            As[(kk + 3) * G1_STRIDE + r] = f2tf32(v.w);
        }
#pragma unroll
        for (int i = 0; i < 4; i++) {
            int f  = tid + i * 256;
            int kr = f >> 5;
            int nc = (f & 31) << 2;
            float4 v = *(const float4*)(W1 + (size_t)(k0 + kr) * HID + nc);
            Bs[kr * G1_STRIDE + nc + 0] = f2tf32(v.x);
            Bs[kr * G1_STRIDE + nc + 1] = f2tf32(v.y);
            Bs[kr * G1_STRIDE + nc + 2] = f2tf32(v.z);
            Bs[kr * G1_STRIDE + nc + 3] = f2tf32(v.w);
        }
        __syncthreads();

#pragma unroll
        for (int ks = 0; ks < 32; ks += 8) {
            uint32_t a[2][4], b[8][2];
#pragma unroll
            for (int mt = 0; mt < 2; mt++) {
                int m0 = wm * 32 + mt * 16;
                a[mt][0] = As[(ks + tig) * G1_STRIDE + m0 + grp];
                a[mt][1] = As[(ks + tig) * G1_STRIDE + m0 + grp + 8];
                a[mt][2] = As[(ks + tig + 4) * G1_STRIDE + m0 + grp];
                a[mt][3] = As[(ks + tig + 4) * G1_STRIDE + m0 + grp + 8];
            }
#pragma unroll
            for (int nt = 0; nt < 8; nt++) {
                int n0 = wn * 64 + nt * 8;
                b[nt][0] = Bs[(ks + tig) * G1_STRIDE + n0 + grp];
                b[nt][1] = Bs[(ks + tig + 4) * G1_STRIDE + n0 + grp];
            }
#pragma unroll
            for (int mt = 0; mt < 2; mt++)
#pragma unroll
                for (int nt = 0; nt < 8; nt++)
                    mma_tf32(c[mt][nt], a[mt], b[nt]);
        }
        __syncthreads();
    }

#pragma unroll
    for (int mt = 0; mt < 2; mt++) {
        int r0 = brow + wm * 32 + mt * 16 + grp;
        int r1 = r0 + 8;
#pragma unroll
        for (int nt = 0; nt < 8; nt++) {
            int col = wn * 64 + nt * 8 + 2 * tig;
            if (r0 < N_NODES)
                *(float2*)(g_h1 + (size_t)r0 * HID + col) =
                    make_float2(c[mt][nt][0], c[mt][nt][1]);
            if (r1 < N_NODES)
                *(float2*)(g_h1 + (size_t)r1 * HID + col) =
                    make_float2(c[mt][nt][2], c[mt][nt][3]);
        }
    }
}

// ===========================================================================
// SpMM1 gather: h2[n] = sum_{e in row n} vals[e] * h1[col[e]]
// Warp per node; lane owns float4 (128 floats = 32 lanes x 4).
// ===========================================================================
__global__ void spmm1_gather_kernel(const int* __restrict__ col,
                                    const float* __restrict__ vals) {
    int node = (blockIdx.x * blockDim.x + threadIdx.x) >> 5;
    if (node >= N_NODES) return;
    int lane  = threadIdx.x & 31;
    int start = g_off[node];
    int end   = g_off[node + 1];

    float4 acc = make_float4(0.f, 0.f, 0.f, 0.f);

    for (int base = start; base < end; base += 32) {
        int m  = end - base; if (m > 32) m = 32;
        int cc = 0; float vv = 0.f;
        if (lane < m) {
            int e = g_perm[base + lane];
            cc = __ldg(col + e);
            vv = __ldg(vals + e);
        }
        int   ct = __shfl_sync(0xffffffffu, cc, 0);
        float vt = __shfl_sync(0xffffffffu, vv, 0);
        float4 s = *((const float4*)(g_h1 + (size_t)ct * HID) + lane);
        for (int t = 1; t < m; t++) {
            int   cn = __shfl_sync(0xffffffffu, cc, t);
            float vn = __shfl_sync(0xffffffffu, vv, t);
            float4 sn = *((const float4*)(g_h1 + (size_t)cn * HID) + lane);
            acc.x = fmaf(vt, s.x, acc.x);
            acc.y = fmaf(vt, s.y, acc.y);
            acc.z = fmaf(vt, s.z, acc.z);
            acc.w = fmaf(vt, s.w, acc.w);
            s = sn; vt = vn;
        }
        acc.x = fmaf(vt, s.x, acc.x);
        acc.y = fmaf(vt, s.y, acc.y);
        acc.z = fmaf(vt, s.z, acc.z);
        acc.w = fmaf(vt, s.w, acc.w);
    }

    *((float4*)(g_h2 + (size_t)node * HID) + lane) = acc;
}

// ===========================================================================
// GEMM2 (TF32 tensor, fused bias+relu): g_h4[M,64] = relu(g_h2+b1) @ W2[128,64]
// Block tile 128x64, BK=32, 256 threads = 8 warps in 4(M)x2(N), warp 32x32.
// ===========================================================================
#define G2B_STRIDE 68
__global__ __launch_bounds__(256) void gemm2_tf32_kernel(const float* __restrict__ B1,
                                                         const float* __restrict__ W2) {
    __shared__ uint32_t As[32 * G1_STRIDE];    // [k][m], 128 wide
    __shared__ uint32_t Bs[32 * G2B_STRIDE];   // [k][n], 64 wide
    __shared__ float    b1s[HID];

    const int tid  = threadIdx.x;
    const int warp = tid >> 5;
    const int lane = tid & 31;
    const int wm   = warp >> 1;
    const int wn   = warp & 1;
    const int brow = blockIdx.x * 128;

    const int grp = lane >> 2;
    const int tig = lane & 3;

    if (tid < HID) b1s[tid] = B1[tid];
    __syncthreads();

    float c[2][4][4];
#pragma unroll
    for (int mt = 0; mt < 2; mt++)
#pragma unroll
        for (int nt = 0; nt < 4; nt++)
#pragma unroll
            for (int i = 0; i < 4; i++) c[mt][nt][i] = 0.f;

#pragma unroll
    for (int k0 = 0; k0 < HID; k0 += 32) {
        // A tile 128x32 from g_h2 with bias+relu
#pragma unroll
        for (int i = 0; i < 4; i++) {
            int f  = tid + i * 256;
            int r  = f >> 3;
            int kk = (f & 7) << 2;
            int gr = brow + r;
            float4 v = make_float4(0.f, 0.f, 0.f, 0.f);
            if (gr < N_NODES) {
                v = *(const float4*)(g_h2 + (size_t)gr * HID + k0 + kk);
                v.x = fmaxf(v.x + b1s[k0 + kk + 0], 0.f);
                v.y = fmaxf(v.y + b1s[k0 + kk + 1], 0.f);
                v.z = fmaxf(v.z + b1s[k0 + kk + 2], 0.f);
                v.w = fmaxf(v.w + b1s[k0 + kk + 3], 0.f);
            }
            As[(kk + 0) * G1_STRIDE + r] = f2tf32(v.x);
            As[(kk + 1) * G1_STRIDE + r] = f2tf32(v.y);
            As[(kk + 2) * G1_STRIDE + r] = f2tf32(v.z);
            As[(kk + 3) * G1_STRIDE + r] = f2tf32(v.w);
        }
        // B tile 32x64 from W2
#pragma unroll
        for (int i = 0; i < 2; i++) {
            int f  = tid + i * 256;
            int kr = f >> 4;
            int nc = (f & 15) << 2;
            float4 v = *(const float4*)(W2 + (size_t)(k0 + kr) * OUTF + nc);
            Bs[kr * G2B_STRIDE + nc + 0] = f2tf32(v.x);
            Bs[kr * G2B_STRIDE + nc + 1] = f2tf32(v.y);
            Bs[kr * G2B_STRIDE + nc + 2] = f2tf32(v.z);
            Bs[kr * G2B_STRIDE + nc + 3] = f2tf32(v.w);
        }
        __syncthreads();

#pragma unroll
        for (int ks = 0; ks < 32; ks += 8) {
            uint32_t a[2][4], b[4][2];
#pragma unroll
            for (int mt = 0; mt < 2; mt++) {
                int m0 = wm * 32 + mt * 16;
                a[mt][0] = As[(ks + tig) * G1_STRIDE + m0 + grp];
                a[mt][1] = As[(ks + tig) * G1_STRIDE + m0 + grp + 8];
                a[mt][2] = As[(ks + tig + 4) * G1_STRIDE + m0 + grp];
                a[mt][3] = As[(ks + tig + 4) * G1_STRIDE + m0 + grp + 8];
            }
#pragma unroll
            for (int nt = 0; nt < 4; nt++) {
                int n0 = wn * 32 + nt * 8;
                b[nt][0] = Bs[(ks + tig) * G2B_STRIDE + n0 + grp];
                b[nt][1] = Bs[(ks + tig + 4) * G2B_STRIDE + n0 + grp];
            }
#pragma unroll
            for (int mt = 0; mt < 2; mt++)
#pragma unroll
                for (int nt = 0; nt < 4; nt++)
                    mma_tf32(c[mt][nt], a[mt], b[nt]);
        }
        __syncthreads();
    }

#pragma unroll
    for (int mt = 0; mt < 2; mt++) {
        int r0 = brow + wm * 32 + mt * 16 + grp;
        int r1 = r0 + 8;
#pragma unroll
        for (int nt = 0; nt < 4; nt++) {
            int col = wn * 32 + nt * 8 + 2 * tig;
            if (r0 < N_NODES)
                *(float2*)(g_h4 + (size_t)r0 * OUTF + col) =
                    make_float2(c[mt][nt][0], c[mt][nt][1]);
            if (r1 < N_NODES)
                *(float2*)(g_h4 + (size_t)r1 * OUTF + col) =
                    make_float2(c[mt][nt][2], c[mt][nt][3]);
        }
    }
}

// ===========================================================================
// SpMM2 gather: out[n] = b2 + sum_{e in row n} vals[e] * h4[col[e]]
// Warp per node; lane owns float2 (64 floats = 32 lanes x 2).
// ===========================================================================
__global__ void spmm2_gather_kernel(const int* __restrict__ col,
                                    const float* __restrict__ vals,
                                    const float* __restrict__ B2,
                                    float* __restrict__ out) {
    int node = (blockIdx.x * blockDim.x + threadIdx.x) >> 5;
    if (node >= N_NODES) return;
    int lane  = threadIdx.x & 31;
    int start = g_off[node];
    int end   = g_off[node + 1];

    float2 acc = *((const float2*)B2 + lane);

    for (int base = start; base < end; base += 32) {
        int m  = end - base; if (m > 32) m = 32;
        int cc = 0; float vv = 0.f;
        if (lane < m) {
            int e = g_perm[base + lane];
            cc = __ldg(col + e);
            vv = __ldg(vals + e);
        }
        int   ct = __shfl_sync(0xffffffffu, cc, 0);
        float vt = __shfl_sync(0xffffffffu, vv, 0);
        float2 s = *((const float2*)(g_h4 + (size_t)ct * OUTF) + lane);
        for (int t = 1; t < m; t++) {
            int   cn = __shfl_sync(0xffffffffu, cc, t);
            float vn = __shfl_sync(0xffffffffu, vv, t);
            float2 sn = *((const float2*)(g_h4 + (size_t)cn * OUTF) + lane);
            acc.x = fmaf(vt, s.x, acc.x);
            acc.y = fmaf(vt, s.y, acc.y);
            s = sn; vt = vn;
        }
        acc.x = fmaf(vt, s.x, acc.x);
        acc.y = fmaf(vt, s.y, acc.y);
    }

    *((float2*)(out + (size_t)node * OUTF) + lane) = acc;
}

// ===========================================================================
extern "C" void kernel_launch(void* const* d_in, const int* in_sizes, int n_in,
                              void* d_out, int out_size) {
    const float* x       = (const float*)d_in[0];
    const float* w1      = (const float*)d_in[1];
    const float* b1      = (const float*)d_in[2];
    const float* w2      = (const float*)d_in[3];
    const float* b2      = (const float*)d_in[4];
    const int*   adj_row = (const int*)d_in[5];
    const int*   adj_col = (const int*)d_in[6];
    const float* vals    = (const float*)d_in[7];
    float*       out     = (float*)d_out;

    (void)in_sizes; (void)n_in; (void)out_size;

    // CSR build (amortized over both SpMMs)
    csr_zero_kernel<<<(N_NODES + 255) / 256, 256>>>();
    csr_count_kernel<<<(N_EDGES + 255) / 256, 256>>>(adj_row);
    csr_scan_kernel<<<1, 1024>>>();
    csr_scatter_kernel<<<(N_EDGES + 255) / 256, 256>>>(adj_row);

    // h1 = X @ W1 (TF32)
    gemm1_tf32_kernel<<<(N_NODES + 127) / 128, 256>>>(x, w1);

    // h2 = A @ h1 (gather)
    {
        long long threads = (long long)N_NODES * 32;
        spmm1_gather_kernel<<<(unsigned)((threads + 255) / 256), 256>>>(adj_col, vals);
    }

    // h4 = relu(h2 + b1) @ W2 (TF32)
    gemm2_tf32_kernel<<<(N_NODES + 127) / 128, 256>>>(b1, w2);

    // out = b2 + A @ h4 (gather)
    {
        long long threads = (long long)N_NODES * 32;
        spmm2_gather_kernel<<<(unsigned)((threads + 255) / 256), 256>>>(adj_col, vals, b2, out);
    }
}